// round 14
// baseline (speedup 1.0000x reference)
#include <cuda_runtime.h>
#include <cuda_bf16.h>
#include <cstdint>

#define NROWS 8192
#define DIM1  1024
#define DIM2  768
#define DOUT  256

#define NTILES2  2048   // 32 x 64 grid of 256x128 tiles
#define CTAS2    148    // 1 per SM, single wave (persistent)

// ---------------- scratch (static __device__ globals; no allocation) ----------------
__device__ __nv_bfloat16 g_Wxb[DOUT * DIM1];
__device__ __nv_bfloat16 g_Wyb[DOUT * DIM2];
__device__ __nv_bfloat16 g_Xn[NROWS * DOUT];   // normalized * log2(e)  (X side)
__device__ __nv_bfloat16 g_Yn[NROWS * DOUT];   // normalized            (Y side)
__device__ float         g_rowsum[NROWS];
__device__ float         g_colsum[NROWS];
__device__ float         g_diag[NROWS];        // diag in log2 domain (= cos * LOG2E)

#define LOG2E 1.4426950408889634f
#define LN2   0.6931471805599453f

// ---------------- helpers ----------------
#define SWZ(x) ((x) ^ (((x) >> 3) & 0x70))

__device__ __forceinline__ void ldsm4(uint32_t& r0, uint32_t& r1, uint32_t& r2, uint32_t& r3, uint32_t a) {
    asm volatile("ldmatrix.sync.aligned.m8n8.x4.shared.b16 {%0,%1,%2,%3}, [%4];"
                 : "=r"(r0), "=r"(r1), "=r"(r2), "=r"(r3) : "r"(a));
}

__device__ __forceinline__ void mma16816(float* c, const uint32_t* a, const uint32_t* b) {
    asm volatile("mma.sync.aligned.m16n8k16.row.col.f32.bf16.bf16.f32 "
                 "{%0,%1,%2,%3},{%4,%5,%6,%7},{%8,%9},{%0,%1,%2,%3};"
                 : "+f"(c[0]), "+f"(c[1]), "+f"(c[2]), "+f"(c[3])
                 : "r"(a[0]), "r"(a[1]), "r"(a[2]), "r"(a[3]), "r"(b[0]), "r"(b[1]));
}

__device__ __forceinline__ float ex2(float x) {
    float r;
    asm("ex2.approx.ftz.f32 %0, %1;" : "=f"(r) : "f"(x));
    return r;
}

// pack two fp32 into bf16x2 (round-to-nearest), result as raw uint32
__device__ __forceinline__ uint32_t pack_bf16x2(float lo, float hi) {
    uint32_t r;
    asm("cvt.rn.bf16x2.f32 %0, %1, %2;" : "=r"(r) : "f"(hi), "f"(lo));
    return r;
}

__device__ __forceinline__ void cpasync16(uint32_t s, const void* g) {
    asm volatile("cp.async.cg.shared.global [%0], [%1], 16;" :: "r"(s), "l"(g));
}

// ============== fused projection + row-normalize (X and Y in ONE launch) ==============
// 512 threads, 64x256 tile, warp grid 2(M) x 8(N), warp tile 32x32.
// A read DIRECTLY from fp32 inputs: LDG float4 x2 -> cvt bf16 -> STS.128, pipelined.
// smem per stage: A 64x64bf16 (8KB) + B 256x64bf16 (32KB) = 40KB; 2 stages = 80KB.
#define PROJ_SMEM 81920

__device__ __forceinline__ void load_B_chunk(const __nv_bfloat16* Bg, int K, uint32_t Bs, int tid) {
#pragma unroll
    for (int i = 0; i < 4; i++) {
        int c = tid + i * 512;
        int row = c >> 3, col = c & 7;
        cpasync16(Bs + SWZ(row * 128 + col * 16), Bg + (size_t)row * K + col * 8);
    }
    asm volatile("cp.async.commit_group;" ::: "memory");
}

// blockIdx.x <  128 : X side (K=DIM1, scale *= LOG2E, zero g_rowsum)
// blockIdx.x >= 128 : Y side (K=DIM2, zero g_colsum)
__global__ void __launch_bounds__(512)
proj_norm_xy(const float* __restrict__ Xraw, const float* __restrict__ Yraw,
             const float* __restrict__ bx, const float* __restrict__ by) {
    extern __shared__ char smem[];
    const uint32_t sb = (uint32_t)__cvta_generic_to_shared(smem);

    const int tid  = threadIdx.x;
    const int lane = tid & 31;
    const int warp = tid >> 5;
    const int wm = warp >> 3;
    const int wn = warp & 7;

    const bool isY = (blockIdx.x >= 128);
    const int mBase = (isY ? (blockIdx.x - 128) : blockIdx.x) * 64;
    const int K = isY ? DIM2 : DIM1;
    const float* Araw = isY ? Yraw : Xraw;
    const __nv_bfloat16* B = isY ? g_Wyb : g_Wxb;
    const float* bias = isY ? by : bx;
    __nv_bfloat16* Out = isY ? g_Yn : g_Xn;

    // A-chunk unit for this thread: row = tid>>3 (64 rows), col8 = tid&7 (8 x 8 elems)
    const int arow = tid >> 3, acol8 = tid & 7;
    const float* aptr = Araw + (size_t)(mBase + arow) * K + acol8 * 8;
    const uint32_t asts = sb + SWZ(arow * 128 + acol8 * 16);

    float4 u0, u1;                 // pipelined A registers (chunk kt)
    u0 = ((const float4*)aptr)[0];
    u1 = ((const float4*)aptr)[1];

    float acc[2][4][4];
#pragma unroll
    for (int i = 0; i < 2; i++)
#pragma unroll
        for (int j = 0; j < 4; j++)
#pragma unroll
            for (int q = 0; q < 4; q++) acc[i][j][q] = 0.f;

    const int KT = K >> 6;
    load_B_chunk(B, K, sb + 8192, tid);

    for (int kt = 0; kt < KT; kt++) {
        const int stage = kt & 1;
        const uint32_t As = sb + stage * 40960;
        const uint32_t Bs = As + 8192;

        // store this chunk's A (registers -> swizzled bf16 smem)
        {
            uint32_t w0 = pack_bf16x2(u0.x, u0.y);
            uint32_t w1 = pack_bf16x2(u0.z, u0.w);
            uint32_t w2 = pack_bf16x2(u1.x, u1.y);
            uint32_t w3 = pack_bf16x2(u1.z, u1.w);
            asm volatile("st.shared.v4.b32 [%0], {%1,%2,%3,%4};"
                         :: "r"(asts + stage * 40960u), "r"(w0), "r"(w1), "r"(w2), "r"(w3));
        }

        if (kt + 1 < KT) {
            // prefetch next B chunk + next A registers
            load_B_chunk(B + (kt + 1) * 64, K, sb + (stage ^ 1) * 40960 + 8192, tid);
            u0 = ((const float4*)(aptr + (kt + 1) * 64))[0];
            u1 = ((const float4*)(aptr + (kt + 1) * 64))[1];
            asm volatile("cp.async.wait_group 1;" ::: "memory");
        } else {
            asm volatile("cp.async.wait_group 0;" ::: "memory");
        }
        __syncthreads();

#pragma unroll
        for (int ks = 0; ks < 4; ks++) {
            uint32_t a[2][4], b[4][2];
#pragma unroll
            for (int mt = 0; mt < 2; mt++) {
                int row = wm * 32 + mt * 16 + (lane & 15);
                int kb  = ks * 32 + ((lane >> 4) << 4);
                ldsm4(a[mt][0], a[mt][1], a[mt][2], a[mt][3], As + SWZ(row * 128 + kb));
            }
#pragma unroll
            for (int np = 0; np < 2; np++) {
                int n  = wn * 32 + np * 16 + (lane & 7) + ((lane >> 4) << 3);
                int kb = ks * 32 + (((lane >> 3) & 1) << 4);
                ldsm4(b[2 * np][0], b[2 * np][1], b[2 * np + 1][0], b[2 * np + 1][1],
                      Bs + SWZ(n * 128 + kb));
            }
#pragma unroll
            for (int mt = 0; mt < 2; mt++)
#pragma unroll
                for (int nt = 0; nt < 4; nt++)
                    mma16816(acc[mt][nt], a[mt], b[nt]);
        }
        __syncthreads();
    }

    // ---- epilogue: bias, sumsq, cross-warp reduce, scale, bf16 store ----
    float* sred   = (float*)smem;            // [64][8]
    float* sscale = sred + 64 * 8;           // [64]

    float p[2][2] = {{0.f, 0.f}, {0.f, 0.f}};
#pragma unroll
    for (int mt = 0; mt < 2; mt++)
#pragma unroll
        for (int nt = 0; nt < 4; nt++) {
            int c = wn * 32 + nt * 8 + ((lane & 3) << 1);
            float b0 = bias[c], b1 = bias[c + 1];
            acc[mt][nt][0] += b0; acc[mt][nt][1] += b1;
            acc[mt][nt][2] += b0; acc[mt][nt][3] += b1;
            p[mt][0] += acc[mt][nt][0] * acc[mt][nt][0] + acc[mt][nt][1] * acc[mt][nt][1];
            p[mt][1] += acc[mt][nt][2] * acc[mt][nt][2] + acc[mt][nt][3] * acc[mt][nt][3];
        }
#pragma unroll
    for (int mt = 0; mt < 2; mt++)
#pragma unroll
        for (int h = 0; h < 2; h++) {
            float v = p[mt][h];
            v += __shfl_xor_sync(0xffffffffu, v, 1);
            v += __shfl_xor_sync(0xffffffffu, v, 2);
            if ((lane & 3) == 0)
                sred[(wm * 32 + mt * 16 + h * 8 + (lane >> 2)) * 8 + wn] = v;
        }
    __syncthreads();
    if (tid < 64) {
        float ss = 0.f;
#pragma unroll
        for (int i = 0; i < 8; i++) ss += sred[tid * 8 + i];
        float sc = 1.0f / fmaxf(sqrtf(ss), 1e-8f);
        if (!isY) sc *= LOG2E;
        sscale[tid] = sc;
        if (!isY) g_rowsum[mBase + tid] = 0.f;
        else      g_colsum[mBase + tid] = 0.f;
    }
    __syncthreads();

#pragma unroll
    for (int mt = 0; mt < 2; mt++)
#pragma unroll
        for (int h = 0; h < 2; h++) {
            int r = wm * 32 + mt * 16 + h * 8 + (lane >> 2);
            float sc = sscale[r];
#pragma unroll
            for (int nt = 0; nt < 4; nt++) {
                int c = wn * 32 + nt * 8 + ((lane & 3) << 1);
                float v0 = acc[mt][nt][2 * h]     * sc;
                float v1 = acc[mt][nt][2 * h + 1] * sc;
                uint32_t w = pack_bf16x2(v0, v1);
                *(uint32_t*)(Out + (size_t)(mBase + r) * DOUT + c) = w;
            }
        }
}

// ======= big GEMM: persistent, 256x128 tile, 64x64 warp tile, 1 CTA/SM, 3-stage ring ==
// smem-crossbar model: per 64-K chunk, LDSM reads = A 32KB x2 + B 16KB x4 = 128KB per
// 2048 MMA-cycles -> 50% crossbar duty at 1 CTA/SM (fully hideable; the 128x128@2CTA
// config needed ~150% and was smem-bound at ~67%).
// smem: 3 stages x (A 32KB + B 16KB) = 144KB; 1 CTA/SM.
#define BIG_SMEM 147456

__device__ __forceinline__ void prefetch_chunk(const __nv_bfloat16* A, const __nv_bfloat16* B,
                                               int g, int bid, uint32_t sb, int tid) {
    const int t = bid + (g >> 2) * CTAS2;
    const int c = g & 3;
    const uint32_t As = sb + (uint32_t)(g % 3) * 49152u;
    const uint32_t Bs = As + 32768;
    const __nv_bfloat16* Ag = A + (size_t)(t >> 6) * 256 * DOUT + c * 64;
    const __nv_bfloat16* Bg = B + (size_t)(t & 63) * 128 * DOUT + c * 64;
#pragma unroll
    for (int i = 0; i < 8; i++) {     // A: 256 rows x 8 col8s = 2048 cells
        int q = tid + i * 256;
        int row = q >> 3, col = q & 7;
        cpasync16(As + SWZ(row * 128 + col * 16), Ag + (size_t)row * DOUT + col * 8);
    }
#pragma unroll
    for (int i = 0; i < 4; i++) {     // B: 128 rows x 8 col8s = 1024 cells
        int q = tid + i * 256;
        int row = q >> 3, col = q & 7;
        cpasync16(Bs + SWZ(row * 128 + col * 16), Bg + (size_t)row * DOUT + col * 8);
    }
    asm volatile("cp.async.commit_group;" ::: "memory");
}

__global__ void __launch_bounds__(256, 1)
gemm_big(const __nv_bfloat16* __restrict__ A, const __nv_bfloat16* __restrict__ B) {
    extern __shared__ char smem[];
    const uint32_t sb = (uint32_t)__cvta_generic_to_shared(smem);

    const int tid  = threadIdx.x;
    const int lane = tid & 31;
    const int warp = tid >> 5;
    const int wmOff = (warp >> 1) * 64;   // 4 warps along M, 64 rows each
    const int wnOff = (warp & 1) * 64;    // 2 warps along N, 64 cols each
    const int bid = blockIdx.x;

    const int myTiles = (NTILES2 - 1 - bid) / CTAS2 + 1;
    const int totalChunks = myTiles * 4;

    prefetch_chunk(A, B, 0, bid, sb, tid);
    if (totalChunks > 1) prefetch_chunk(A, B, 1, bid, sb, tid);

    int t = bid;
    for (int ti = 0; ti < myTiles; ti++, t += CTAS2) {
        const int mBase = (t >> 6) * 256;
        const int nBase = (t & 63) * 128;

        float acc[4][8][4];
#pragma unroll
        for (int i = 0; i < 4; i++)
#pragma unroll
            for (int j = 0; j < 8; j++)
#pragma unroll
                for (int q = 0; q < 4; q++) acc[i][j][q] = 0.f;

#pragma unroll
        for (int c = 0; c < 4; c++) {
            const int g = ti * 4 + c;
            asm volatile("cp.async.wait_group 1;" ::: "memory");
            __syncthreads();
            if (g + 2 < totalChunks) prefetch_chunk(A, B, g + 2, bid, sb, tid);

            const uint32_t As = sb + (uint32_t)(g % 3) * 49152u;
            const uint32_t Bs = As + 32768;

#pragma unroll
            for (int ks = 0; ks < 4; ks++) {
                uint32_t a[4][4], b[8][2];
#pragma unroll
                for (int mt = 0; mt < 4; mt++) {
                    int row = wmOff + mt * 16 + (lane & 15);
                    int kb  = ks * 32 + ((lane >> 4) << 4);
                    ldsm4(a[mt][0], a[mt][1], a[mt][2], a[mt][3], As + SWZ(row * 128 + kb));
                }
#pragma unroll
                for (int np = 0; np < 4; np++) {
                    int n  = wnOff + np * 16 + (lane & 7) + ((lane >> 4) << 3);
                    int kb = ks * 32 + (((lane >> 3) & 1) << 4);
                    ldsm4(b[2 * np][0], b[2 * np][1], b[2 * np + 1][0], b[2 * np + 1][1],
                          Bs + SWZ(n * 128 + kb));
                }
#pragma unroll
                for (int mt = 0; mt < 4; mt++)
#pragma unroll
                    for (int nt = 0; nt < 8; nt++)
                        mma16816(acc[mt][nt], a[mt], b[nt]);
            }
        }

        // ---- epilogue: diag capture, exp, row/col partials ----
        const bool diagSpan = (nBase >= mBase) && (nBase < mBase + 256);
        float rp[4][2], cp[8][2];
#pragma unroll
        for (int i = 0; i < 4; i++) { rp[i][0] = rp[i][1] = 0.f; }
#pragma unroll
        for (int i = 0; i < 8; i++) { cp[i][0] = cp[i][1] = 0.f; }

#pragma unroll
        for (int mt = 0; mt < 4; mt++) {
#pragma unroll
            for (int nt = 0; nt < 8; nt++) {
                if (diagSpan) {
#pragma unroll
                    for (int q = 0; q < 4; q++) {
                        int r  = mBase + wmOff + mt * 16 + (lane >> 2) + ((q >> 1) << 3);
                        int c2 = nBase + wnOff + nt * 8 + ((lane & 3) << 1) + (q & 1);
                        if (r == c2) g_diag[r] = acc[mt][nt][q];  // log2 domain
                    }
                }
                float e0 = ex2(acc[mt][nt][0]);
                float e1 = ex2(acc[mt][nt][1]);
                float e2 = ex2(acc[mt][nt][2]);
                float e3 = ex2(acc[mt][nt][3]);
                rp[mt][0] += e0 + e1;
                rp[mt][1] += e2 + e3;
                cp[nt][0] += e0 + e2;
                cp[nt][1] += e1 + e3;
            }
        }

#pragma unroll
        for (int mt = 0; mt < 4; mt++)
#pragma unroll
            for (int h = 0; h < 2; h++) {
                float v = rp[mt][h];
                v += __shfl_xor_sync(0xffffffffu, v, 1);
                v += __shfl_xor_sync(0xffffffffu, v, 2);
                if ((lane & 3) == 0)
                    atomicAdd(&g_rowsum[mBase + wmOff + mt * 16 + h * 8 + (lane >> 2)], v);
            }
#pragma unroll
        for (int nt = 0; nt < 8; nt++)
#pragma unroll
            for (int j = 0; j < 2; j++) {
                float v = cp[nt][j];
                v += __shfl_xor_sync(0xffffffffu, v, 4);
                v += __shfl_xor_sync(0xffffffffu, v, 8);
                v += __shfl_xor_sync(0xffffffffu, v, 16);
                if (lane < 4)
                    atomicAdd(&g_colsum[nBase + wnOff + nt * 8 + ((lane & 3) << 1) + j], v);
            }
    }
}

// ---------------- small kernels ----------------
// weights-only fp32 -> bf16 (X/Y are consumed directly by proj_norm_xy)
__global__ void conv_w(const float* __restrict__ Wx, const float* __restrict__ Wy) {
    const int NWX = DOUT * DIM1 / 4, NWY = DOUT * DIM2 / 4;
    int j = blockIdx.x * blockDim.x + threadIdx.x;
    const float* src;
    __nv_bfloat16* dst;
    if (j < NWX) { src = Wx; dst = g_Wxb; }
    else {
        j -= NWX;
        if (j >= NWY) return;
        src = Wy; dst = g_Wyb;
    }
    float4 v = ((const float4*)src)[j];
    ((uint32_t*)dst)[2 * j]     = pack_bf16x2(v.x, v.y);
    ((uint32_t*)dst)[2 * j + 1] = pack_bf16x2(v.z, v.w);
}

// out[j] = log(colsum - pos) + log(rowsum - pos) - 2*d,  d = diag*ln2, pos = exp(d)
__global__ void finalize(float* __restrict__ out) {
    int j = blockIdx.x * blockDim.x + threadIdx.x;
    if (j < NROWS) {
        float d = g_diag[j] * LN2;
        float pos = __expf(d);
        out[j] = logf(g_colsum[j] - pos) + logf(g_rowsum[j] - pos) - 2.0f * d;
    }
}

// ---------------- launch ----------------
static void* sym_addr(const void* s) {
    void* p = nullptr;
    cudaGetSymbolAddress(&p, s);
    return p;
}

extern "C" void kernel_launch(void* const* d_in, const int* in_sizes, int n_in,
                              void* d_out, int out_size) {
    const float* X  = (const float*)d_in[0];
    const float* Y  = (const float*)d_in[1];
    const float* Wx = (const float*)d_in[2];
    const float* bx = (const float*)d_in[3];
    const float* Wy = (const float*)d_in[4];
    const float* by = (const float*)d_in[5];

    __nv_bfloat16* Xn = (__nv_bfloat16*)sym_addr(g_Xn);
    __nv_bfloat16* Yn = (__nv_bfloat16*)sym_addr(g_Yn);

    cudaFuncSetAttribute(proj_norm_xy, cudaFuncAttributeMaxDynamicSharedMemorySize, PROJ_SMEM);
    cudaFuncSetAttribute(gemm_big,     cudaFuncAttributeMaxDynamicSharedMemorySize, BIG_SMEM);

    // 0) weight conversion only (~0.9 MB)
    {
        const int total4 = (DOUT * DIM1 + DOUT * DIM2) / 4;
        conv_w<<<(total4 + 255) / 256, 256>>>(Wx, Wy);
    }

    // 1) fused projection + normalize for BOTH X and Y; A read straight from fp32 inputs
    proj_norm_xy<<<256, 512, PROJ_SMEM>>>(X, Y, bx, by);

    // 2) persistent big GEMM (256x128 tiles) with fused 2^x / rowsum / colsum / diag
    gemm_big<<<CTAS2, 256, BIG_SMEM>>>(Xn, Yn);

    // 3) elementwise finalize
    finalize<<<NROWS / 256, 256>>>((float*)d_out);
}

// round 15
// speedup vs baseline: 1.0884x; 1.0884x over previous
#include <cuda_runtime.h>
#include <cuda_bf16.h>
#include <cstdint>

#define NROWS 8192
#define DIM1  1024
#define DIM2  768
#define DOUT  256

#define NTILES   4096   // 64 x 64 grid of 128x128 tiles
#define CTAS     296    // 2 per SM, single wave

// ---------------- scratch (static __device__ globals; no allocation) ----------------
__device__ __nv_bfloat16 g_Wxb[DOUT * DIM1];
__device__ __nv_bfloat16 g_Wyb[DOUT * DIM2];
__device__ __nv_bfloat16 g_Xn[NROWS * DOUT];   // normalized * log2(e)  (X side)
__device__ __nv_bfloat16 g_Yn[NROWS * DOUT];   // normalized            (Y side)
__device__ float         g_rowsum[NROWS];
__device__ float         g_colsum[NROWS];
__device__ float         g_diag[NROWS];        // diag in log2 domain (= cos * LOG2E)

#define LOG2E 1.4426950408889634f
#define LN2   0.6931471805599453f

// ---------------- helpers ----------------
#define SWZ(x) ((x) ^ (((x) >> 3) & 0x70))

__device__ __forceinline__ void ldsm4(uint32_t& r0, uint32_t& r1, uint32_t& r2, uint32_t& r3, uint32_t a) {
    asm volatile("ldmatrix.sync.aligned.m8n8.x4.shared.b16 {%0,%1,%2,%3}, [%4];"
                 : "=r"(r0), "=r"(r1), "=r"(r2), "=r"(r3) : "r"(a));
}

__device__ __forceinline__ void mma16816(float* c, const uint32_t* a, const uint32_t* b) {
    asm volatile("mma.sync.aligned.m16n8k16.row.col.f32.bf16.bf16.f32 "
                 "{%0,%1,%2,%3},{%4,%5,%6,%7},{%8,%9},{%0,%1,%2,%3};"
                 : "+f"(c[0]), "+f"(c[1]), "+f"(c[2]), "+f"(c[3])
                 : "r"(a[0]), "r"(a[1]), "r"(a[2]), "r"(a[3]), "r"(b[0]), "r"(b[1]));
}

__device__ __forceinline__ float ex2(float x) {
    float r;
    asm("ex2.approx.ftz.f32 %0, %1;" : "=f"(r) : "f"(x));
    return r;
}

// pack two fp32 into bf16x2 (round-to-nearest), result as raw uint32
__device__ __forceinline__ uint32_t pack_bf16x2(float lo, float hi) {
    uint32_t r;
    asm("cvt.rn.bf16x2.f32 %0, %1, %2;" : "=r"(r) : "f"(hi), "f"(lo));
    return r;
}

__device__ __forceinline__ void cpasync16(uint32_t s, const void* g) {
    asm volatile("cp.async.cg.shared.global [%0], [%1], 16;" :: "r"(s), "l"(g));
}

// ============== fused projection + row-normalize (X and Y in ONE launch) ==============
// 512 threads, 64x256 tile, warp grid 2(M) x 8(N), warp tile 32x32.
// A read DIRECTLY from fp32 inputs: LDG float4 x2 -> cvt bf16 -> STS.128, pipelined.
// smem per stage: A 64x64bf16 (8KB) + B 256x64bf16 (32KB) = 40KB; 2 stages = 80KB.
#define PROJ_SMEM 81920

__device__ __forceinline__ void load_B_chunk(const __nv_bfloat16* Bg, int K, uint32_t Bs, int tid) {
#pragma unroll
    for (int i = 0; i < 4; i++) {
        int c = tid + i * 512;
        int row = c >> 3, col = c & 7;
        cpasync16(Bs + SWZ(row * 128 + col * 16), Bg + (size_t)row * K + col * 8);
    }
    asm volatile("cp.async.commit_group;" ::: "memory");
}

// blockIdx.x <  128 : X side (K=DIM1, scale *= LOG2E, zero g_rowsum)
// blockIdx.x >= 128 : Y side (K=DIM2, zero g_colsum)
__global__ void __launch_bounds__(512)
proj_norm_xy(const float* __restrict__ Xraw, const float* __restrict__ Yraw,
             const float* __restrict__ bx, const float* __restrict__ by) {
    extern __shared__ char smem[];
    const uint32_t sb = (uint32_t)__cvta_generic_to_shared(smem);

    const int tid  = threadIdx.x;
    const int lane = tid & 31;
    const int warp = tid >> 5;
    const int wm = warp >> 3;
    const int wn = warp & 7;

    const bool isY = (blockIdx.x >= 128);
    const int mBase = (isY ? (blockIdx.x - 128) : blockIdx.x) * 64;
    const int K = isY ? DIM2 : DIM1;
    const float* Araw = isY ? Yraw : Xraw;
    const __nv_bfloat16* B = isY ? g_Wyb : g_Wxb;
    const float* bias = isY ? by : bx;
    __nv_bfloat16* Out = isY ? g_Yn : g_Xn;

    // A-chunk unit for this thread: row = tid>>3 (64 rows), col8 = tid&7 (8 x 8 elems)
    const int arow = tid >> 3, acol8 = tid & 7;
    const float* aptr = Araw + (size_t)(mBase + arow) * K + acol8 * 8;
    const uint32_t asts = sb + SWZ(arow * 128 + acol8 * 16);

    float4 u0, u1;                 // pipelined A registers (chunk kt)
    u0 = ((const float4*)aptr)[0];
    u1 = ((const float4*)aptr)[1];

    float acc[2][4][4];
#pragma unroll
    for (int i = 0; i < 2; i++)
#pragma unroll
        for (int j = 0; j < 4; j++)
#pragma unroll
            for (int q = 0; q < 4; q++) acc[i][j][q] = 0.f;

    const int KT = K >> 6;
    load_B_chunk(B, K, sb + 8192, tid);

    for (int kt = 0; kt < KT; kt++) {
        const int stage = kt & 1;
        const uint32_t As = sb + stage * 40960;
        const uint32_t Bs = As + 8192;

        // store this chunk's A (registers -> swizzled bf16 smem)
        {
            uint32_t w0 = pack_bf16x2(u0.x, u0.y);
            uint32_t w1 = pack_bf16x2(u0.z, u0.w);
            uint32_t w2 = pack_bf16x2(u1.x, u1.y);
            uint32_t w3 = pack_bf16x2(u1.z, u1.w);
            asm volatile("st.shared.v4.b32 [%0], {%1,%2,%3,%4};"
                         :: "r"(asts + stage * 40960u), "r"(w0), "r"(w1), "r"(w2), "r"(w3));
        }

        if (kt + 1 < KT) {
            // prefetch next B chunk + next A registers
            load_B_chunk(B + (kt + 1) * 64, K, sb + (stage ^ 1) * 40960 + 8192, tid);
            u0 = ((const float4*)(aptr + (kt + 1) * 64))[0];
            u1 = ((const float4*)(aptr + (kt + 1) * 64))[1];
            asm volatile("cp.async.wait_group 1;" ::: "memory");
        } else {
            asm volatile("cp.async.wait_group 0;" ::: "memory");
        }
        __syncthreads();

#pragma unroll
        for (int ks = 0; ks < 4; ks++) {
            uint32_t a[2][4], b[4][2];
#pragma unroll
            for (int mt = 0; mt < 2; mt++) {
                int row = wm * 32 + mt * 16 + (lane & 15);
                int kb  = ks * 32 + ((lane >> 4) << 4);
                ldsm4(a[mt][0], a[mt][1], a[mt][2], a[mt][3], As + SWZ(row * 128 + kb));
            }
#pragma unroll
            for (int np = 0; np < 2; np++) {
                int n  = wn * 32 + np * 16 + (lane & 7) + ((lane >> 4) << 3);
                int kb = ks * 32 + (((lane >> 3) & 1) << 4);
                ldsm4(b[2 * np][0], b[2 * np][1], b[2 * np + 1][0], b[2 * np + 1][1],
                      Bs + SWZ(n * 128 + kb));
            }
#pragma unroll
            for (int mt = 0; mt < 2; mt++)
#pragma unroll
                for (int nt = 0; nt < 4; nt++)
                    mma16816(acc[mt][nt], a[mt], b[nt]);
        }
        __syncthreads();
    }

    // ---- epilogue: bias, sumsq, cross-warp reduce, scale, bf16 store ----
    float* sred   = (float*)smem;            // [64][8]
    float* sscale = sred + 64 * 8;           // [64]

    float p[2][2] = {{0.f, 0.f}, {0.f, 0.f}};
#pragma unroll
    for (int mt = 0; mt < 2; mt++)
#pragma unroll
        for (int nt = 0; nt < 4; nt++) {
            int c = wn * 32 + nt * 8 + ((lane & 3) << 1);
            float b0 = bias[c], b1 = bias[c + 1];
            acc[mt][nt][0] += b0; acc[mt][nt][1] += b1;
            acc[mt][nt][2] += b0; acc[mt][nt][3] += b1;
            p[mt][0] += acc[mt][nt][0] * acc[mt][nt][0] + acc[mt][nt][1] * acc[mt][nt][1];
            p[mt][1] += acc[mt][nt][2] * acc[mt][nt][2] + acc[mt][nt][3] * acc[mt][nt][3];
        }
#pragma unroll
    for (int mt = 0; mt < 2; mt++)
#pragma unroll
        for (int h = 0; h < 2; h++) {
            float v = p[mt][h];
            v += __shfl_xor_sync(0xffffffffu, v, 1);
            v += __shfl_xor_sync(0xffffffffu, v, 2);
            if ((lane & 3) == 0)
                sred[(wm * 32 + mt * 16 + h * 8 + (lane >> 2)) * 8 + wn] = v;
        }
    __syncthreads();
    if (tid < 64) {
        float ss = 0.f;
#pragma unroll
        for (int i = 0; i < 8; i++) ss += sred[tid * 8 + i];
        float sc = 1.0f / fmaxf(sqrtf(ss), 1e-8f);
        if (!isY) sc *= LOG2E;
        sscale[tid] = sc;
        if (!isY) g_rowsum[mBase + tid] = 0.f;
        else      g_colsum[mBase + tid] = 0.f;
    }
    __syncthreads();

#pragma unroll
    for (int mt = 0; mt < 2; mt++)
#pragma unroll
        for (int h = 0; h < 2; h++) {
            int r = wm * 32 + mt * 16 + h * 8 + (lane >> 2);
            float sc = sscale[r];
#pragma unroll
            for (int nt = 0; nt < 4; nt++) {
                int c = wn * 32 + nt * 8 + ((lane & 3) << 1);
                float v0 = acc[mt][nt][2 * h]     * sc;
                float v1 = acc[mt][nt][2 * h + 1] * sc;
                uint32_t w = pack_bf16x2(v0, v1);
                *(uint32_t*)(Out + (size_t)(mBase + r) * DOUT + c) = w;
            }
        }
}

// ======= big GEMM: persistent CTAs, 128x128 tile, 64x32 warp tile, 3-stage ring ======
// smem: 3 stages x (A 16KB + B 16KB) = 96KB; 2 CTAs/SM (192KB of 228KB).
// CHAMPION CONFIG (measured 135.2us total, three times). Do not perturb: any
// code added under the (256,2) register cap poisons the mainloop (rounds 11/12:
// +34us); 1 CTA/SM variants expose the epilogue (rounds 5/6/14: +10..31us).
#define BIG_SMEM 98304

__device__ __forceinline__ void prefetch_chunk(const __nv_bfloat16* A, const __nv_bfloat16* B,
                                               int g, int bid, uint32_t sb, int tid) {
    const int t = bid + (g >> 2) * CTAS;
    const int c = g & 3;
    const uint32_t As = sb + (uint32_t)(g % 3) * 32768u;
    const uint32_t Bs = As + 16384;
    const __nv_bfloat16* Ag = A + (size_t)(t >> 6) * 128 * DOUT + c * 64;
    const __nv_bfloat16* Bg = B + (size_t)(t & 63) * 128 * DOUT + c * 64;
#pragma unroll
    for (int i = 0; i < 4; i++) {
        int q = tid + i * 256;
        int row = q >> 3, col = q & 7;
        cpasync16(As + SWZ(row * 128 + col * 16), Ag + (size_t)row * DOUT + col * 8);
        cpasync16(Bs + SWZ(row * 128 + col * 16), Bg + (size_t)row * DOUT + col * 8);
    }
    asm volatile("cp.async.commit_group;" ::: "memory");
}

__global__ void __launch_bounds__(256, 2)
gemm_big(const __nv_bfloat16* __restrict__ A, const __nv_bfloat16* __restrict__ B) {
    extern __shared__ char smem[];
    const uint32_t sb = (uint32_t)__cvta_generic_to_shared(smem);

    const int tid  = threadIdx.x;
    const int lane = tid & 31;
    const int warp = tid >> 5;
    const int wmOff = (warp >> 2) * 64;   // 2 warps along M, 64 rows each
    const int wnOff = (warp & 3) * 32;    // 4 warps along N, 32 cols each
    const int bid = blockIdx.x;

    const int myTiles = (NTILES - 1 - bid) / CTAS + 1;
    const int totalChunks = myTiles * 4;

    prefetch_chunk(A, B, 0, bid, sb, tid);
    if (totalChunks > 1) prefetch_chunk(A, B, 1, bid, sb, tid);

    int t = bid;
    for (int ti = 0; ti < myTiles; ti++, t += CTAS) {
        const int mBase = (t >> 6) * 128;
        const int nBase = (t & 63) * 128;

        float acc[4][4][4];
#pragma unroll
        for (int i = 0; i < 4; i++)
#pragma unroll
            for (int j = 0; j < 4; j++)
#pragma unroll
                for (int q = 0; q < 4; q++) acc[i][j][q] = 0.f;

#pragma unroll
        for (int c = 0; c < 4; c++) {
            const int g = ti * 4 + c;
            asm volatile("cp.async.wait_group 1;" ::: "memory");
            __syncthreads();
            if (g + 2 < totalChunks) prefetch_chunk(A, B, g + 2, bid, sb, tid);

            const uint32_t As = sb + (uint32_t)(g % 3) * 32768u;
            const uint32_t Bs = As + 16384;

#pragma unroll
            for (int ks = 0; ks < 4; ks++) {
                uint32_t a[4][4], b[4][2];
#pragma unroll
                for (int mt = 0; mt < 4; mt++) {
                    int row = wmOff + mt * 16 + (lane & 15);
                    int kb  = ks * 32 + ((lane >> 4) << 4);
                    ldsm4(a[mt][0], a[mt][1], a[mt][2], a[mt][3], As + SWZ(row * 128 + kb));
                }
#pragma unroll
                for (int np = 0; np < 2; np++) {
                    int n  = wnOff + np * 16 + (lane & 7) + ((lane >> 4) << 3);
                    int kb = ks * 32 + (((lane >> 3) & 1) << 4);
                    ldsm4(b[2 * np][0], b[2 * np][1], b[2 * np + 1][0], b[2 * np + 1][1],
                          Bs + SWZ(n * 128 + kb));
                }
#pragma unroll
                for (int mt = 0; mt < 4; mt++)
#pragma unroll
                    for (int nt = 0; nt < 4; nt++)
                        mma16816(acc[mt][nt], a[mt], b[nt]);
            }
        }

        // ---- epilogue: diag capture (diagonal tiles only), exp, row/col partials ----
        const bool diagTile = (mBase == nBase);
        float rp[4][2], cp[4][2];
#pragma unroll
        for (int i = 0; i < 4; i++) { rp[i][0] = rp[i][1] = 0.f; cp[i][0] = cp[i][1] = 0.f; }

#pragma unroll
        for (int mt = 0; mt < 4; mt++) {
#pragma unroll
            for (int nt = 0; nt < 4; nt++) {
                if (diagTile) {
#pragma unroll
                    for (int q = 0; q < 4; q++) {
                        int r = wmOff + mt * 16 + (lane >> 2) + ((q >> 1) << 3);
                        int c2 = wnOff + nt * 8 + ((lane & 3) << 1) + (q & 1);
                        if (r == c2) g_diag[mBase + r] = acc[mt][nt][q];  // log2 domain
                    }
                }
                float e0 = ex2(acc[mt][nt][0]);
                float e1 = ex2(acc[mt][nt][1]);
                float e2 = ex2(acc[mt][nt][2]);
                float e3 = ex2(acc[mt][nt][3]);
                rp[mt][0] += e0 + e1;
                rp[mt][1] += e2 + e3;
                cp[nt][0] += e0 + e2;
                cp[nt][1] += e1 + e3;
            }
        }

#pragma unroll
        for (int mt = 0; mt < 4; mt++)
#pragma unroll
            for (int h = 0; h < 2; h++) {
                float v = rp[mt][h];
                v += __shfl_xor_sync(0xffffffffu, v, 1);
                v += __shfl_xor_sync(0xffffffffu, v, 2);
                if ((lane & 3) == 0)
                    atomicAdd(&g_rowsum[mBase + wmOff + mt * 16 + h * 8 + (lane >> 2)], v);
            }
#pragma unroll
        for (int nt = 0; nt < 4; nt++)
#pragma unroll
            for (int j = 0; j < 2; j++) {
                float v = cp[nt][j];
                v += __shfl_xor_sync(0xffffffffu, v, 4);
                v += __shfl_xor_sync(0xffffffffu, v, 8);
                v += __shfl_xor_sync(0xffffffffu, v, 16);
                if (lane < 4)
                    atomicAdd(&g_colsum[nBase + wnOff + nt * 8 + ((lane & 3) << 1) + j], v);
            }
    }
}

// ---------------- small kernels ----------------
// weights-only fp32 -> bf16 (X/Y are consumed directly by proj_norm_xy)
__global__ void conv_w(const float* __restrict__ Wx, const float* __restrict__ Wy) {
    const int NWX = DOUT * DIM1 / 4, NWY = DOUT * DIM2 / 4;
    int j = blockIdx.x * blockDim.x + threadIdx.x;
    const float* src;
    __nv_bfloat16* dst;
    if (j < NWX) { src = Wx; dst = g_Wxb; }
    else {
        j -= NWX;
        if (j >= NWY) return;
        src = Wy; dst = g_Wyb;
    }
    float4 v = ((const float4*)src)[j];
    ((uint32_t*)dst)[2 * j]     = pack_bf16x2(v.x, v.y);
    ((uint32_t*)dst)[2 * j + 1] = pack_bf16x2(v.z, v.w);
}

// out[j] = log(colsum - pos) + log(rowsum - pos) - 2*d,  d = diag*ln2, pos = exp(d)
__global__ void finalize(float* __restrict__ out) {
    int j = blockIdx.x * blockDim.x + threadIdx.x;
    if (j < NROWS) {
        float d = g_diag[j] * LN2;
        float pos = __expf(d);
        out[j] = logf(g_colsum[j] - pos) + logf(g_rowsum[j] - pos) - 2.0f * d;
    }
}

// ---------------- launch ----------------
static void* sym_addr(const void* s) {
    void* p = nullptr;
    cudaGetSymbolAddress(&p, s);
    return p;
}

extern "C" void kernel_launch(void* const* d_in, const int* in_sizes, int n_in,
                              void* d_out, int out_size) {
    const float* X  = (const float*)d_in[0];
    const float* Y  = (const float*)d_in[1];
    const float* Wx = (const float*)d_in[2];
    const float* bx = (const float*)d_in[3];
    const float* Wy = (const float*)d_in[4];
    const float* by = (const float*)d_in[5];

    __nv_bfloat16* Xn = (__nv_bfloat16*)sym_addr(g_Xn);
    __nv_bfloat16* Yn = (__nv_bfloat16*)sym_addr(g_Yn);

    cudaFuncSetAttribute(proj_norm_xy, cudaFuncAttributeMaxDynamicSharedMemorySize, PROJ_SMEM);
    cudaFuncSetAttribute(gemm_big,     cudaFuncAttributeMaxDynamicSharedMemorySize, BIG_SMEM);

    // 0) weight conversion only (~0.9 MB)
    {
        const int total4 = (DOUT * DIM1 + DOUT * DIM2) / 4;
        conv_w<<<(total4 + 255) / 256, 256>>>(Wx, Wy);
    }

    // 1) fused projection + normalize for BOTH X and Y; A read straight from fp32 inputs
    proj_norm_xy<<<256, 512, PROJ_SMEM>>>(X, Y, bx, by);

    // 2) persistent big GEMM with fused 2^x / rowsum / colsum / diag
    gemm_big<<<CTAS, 256, BIG_SMEM>>>(Xn, Yn);

    // 3) elementwise finalize
    finalize<<<NROWS / 256, 256>>>((float*)d_out);
}